// round 3
// baseline (speedup 1.0000x reference)
#include <cuda_runtime.h>
#include <cuda_bf16.h>
#include <cstdint>

// Problem constants
#define BB 512
#define TT 128
#define II 512
#define HH 512
#define CC 97
#define SS 26
#define G4H 2048           // 4*H
#define WIH_LD 609         // I + C

// ---------------- device scratch (static, no allocs) ----------------
__device__ float g_feat[(size_t)BB * TT * HH];     // 128 MB
__device__ float g_h[BB * HH];
__device__ float g_c[BB * HH];
__device__ float g_hp[BB * HH];
__device__ float g_ctx[BB * II];
__device__ float g_gates[BB * G4H];
__device__ float g_outh[(size_t)BB * SS * HH];     // 27 MB
__device__ float g_Wx[G4H * II];                   // W_ih[:, :I] packed contiguous
__device__ float g_WohT[CC * G4H];                 // W_ih[:, I:]^T  [class][4H]
__device__ float g_bg[G4H];                        // b_ih + b_hh

// ---------------- pack / init kernel ----------------
__global__ void pack_kernel(const float* __restrict__ W_ih,
                            const float* __restrict__ b_ih,
                            const float* __restrict__ b_hh)
{
    const int stride = gridDim.x * blockDim.x;
    const int t0 = blockIdx.x * blockDim.x + threadIdx.x;
    for (int i = t0; i < G4H * II; i += stride) {
        int r = i >> 9, cc = i & 511;
        g_Wx[i] = W_ih[r * WIH_LD + cc];
    }
    for (int i = t0; i < CC * G4H; i += stride) {
        int cls = i >> 11, j = i & 2047;
        g_WohT[i] = W_ih[j * WIH_LD + II + cls];
    }
    for (int i = t0; i < G4H; i += stride) g_bg[i] = b_ih[i] + b_hh[i];
    for (int i = t0; i < BB * HH; i += stride) { g_h[i] = 0.f; g_c[i] = 0.f; }
}

// ---------------- generic tiled GEMM: C[M,N] = A[M,K] * B[N,K]^T (+C | +bias) ----------------
// A,B row-major with leading dim == K (K % 16 == 0, rows 16B-aligned).
template<int BM, int BN, int TM, int TN>
__global__ __launch_bounds__(256)
void gemm_tn(const float* __restrict__ A, const float* __restrict__ B,
             const float* __restrict__ bias, float* __restrict__ C,
             int M, int N, int K, int ldc, int accumulate)
{
    constexpr int BK = 16;
    __shared__ float As[BK][BM + 4];
    __shared__ float Bs[BK][BN + 4];

    const int tid = threadIdx.x;
    const int tx = tid & 15;         // 16 cols of threads
    const int ty = tid >> 4;         // 16 rows of threads
    const int bm = blockIdx.x * BM;
    const int bn = blockIdx.y * BN;

    float acc[TM][TN];
#pragma unroll
    for (int i = 0; i < TM; ++i)
#pragma unroll
        for (int j = 0; j < TN; ++j) acc[i][j] = 0.f;

    const int lrow = tid >> 2;            // 0..63
    const int lcol = (tid & 3) << 2;      // 0,4,8,12

    for (int k0 = 0; k0 < K; k0 += BK) {
#pragma unroll
        for (int p = 0; p < BM / 64; ++p) {
            int r = lrow + p * 64;
            int gr = bm + r;
            float4 v = make_float4(0.f, 0.f, 0.f, 0.f);
            if (gr < M) v = *reinterpret_cast<const float4*>(A + (size_t)gr * K + k0 + lcol);
            As[lcol + 0][r] = v.x; As[lcol + 1][r] = v.y;
            As[lcol + 2][r] = v.z; As[lcol + 3][r] = v.w;
        }
#pragma unroll
        for (int p = 0; p < BN / 64; ++p) {
            int r = lrow + p * 64;
            int gr = bn + r;
            float4 v = make_float4(0.f, 0.f, 0.f, 0.f);
            if (gr < N) v = *reinterpret_cast<const float4*>(B + (size_t)gr * K + k0 + lcol);
            Bs[lcol + 0][r] = v.x; Bs[lcol + 1][r] = v.y;
            Bs[lcol + 2][r] = v.z; Bs[lcol + 3][r] = v.w;
        }
        __syncthreads();

#pragma unroll
        for (int kk = 0; kk < BK; ++kk) {
            float a[TM], bb[TN];
#pragma unroll
            for (int i = 0; i < TM; i += 4)
                *reinterpret_cast<float4*>(&a[i]) =
                    *reinterpret_cast<const float4*>(&As[kk][ty * TM + i]);
#pragma unroll
            for (int j = 0; j < TN; j += 4)
                *reinterpret_cast<float4*>(&bb[j]) =
                    *reinterpret_cast<const float4*>(&Bs[kk][tx * TN + j]);
#pragma unroll
            for (int i = 0; i < TM; ++i)
#pragma unroll
                for (int j = 0; j < TN; ++j)
                    acc[i][j] = fmaf(a[i], bb[j], acc[i][j]);
        }
        __syncthreads();
    }

#pragma unroll
    for (int i = 0; i < TM; ++i) {
        int gm = bm + ty * TM + i;
        if (gm >= M) continue;
#pragma unroll
        for (int j = 0; j < TN; ++j) {
            int gn = bn + tx * TN + j;
            if (gn >= N) continue;
            float v = acc[i][j];
            if (accumulate) v += C[(size_t)gm * ldc + gn];
            else if (bias)  v += bias[gn];
            C[(size_t)gm * ldc + gn] = v;
        }
    }
}

// ---------------- fused attention: energies + softmax + context ----------------
// one block per batch row b (512 blocks, 256 threads)
__global__ __launch_bounds__(256)
void att_kernel(const float* __restrict__ batch_H, const float* __restrict__ feat,
                const float* __restrict__ hp, const float* __restrict__ w_score,
                float* __restrict__ ctx)
{
    __shared__ float hp_sh[HH];
    __shared__ float ws_sh[HH];
    __shared__ float e_sh[TT];
    __shared__ float red_sh[2];

    const int b = blockIdx.x;
    const int tid = threadIdx.x;

    hp_sh[tid]       = hp[b * HH + tid];
    hp_sh[tid + 256] = hp[b * HH + 256 + tid];
    ws_sh[tid]       = w_score[tid];
    ws_sh[tid + 256] = w_score[tid + 256];
    __syncthreads();

    const int warp = tid >> 5, lane = tid & 31;

    // energies: e[t] = sum_h tanh(feat + hp) * w
    for (int t = warp; t < TT; t += 8) {
        const float* fr = feat + ((size_t)b * TT + t) * HH;
        float acc = 0.f;
#pragma unroll
        for (int j = 0; j < 16; ++j) {
            int hh = j * 32 + lane;
            float x = fr[hh] + hp_sh[hh];
            float th;
            asm("tanh.approx.f32 %0, %1;" : "=f"(th) : "f"(x));
            acc = fmaf(th, ws_sh[hh], acc);
        }
#pragma unroll
        for (int o = 16; o > 0; o >>= 1) acc += __shfl_xor_sync(0xffffffffu, acc, o);
        if (lane == 0) e_sh[t] = acc;
    }
    __syncthreads();

    // softmax over T=128
    if (tid < 32) {
        float m = fmaxf(fmaxf(e_sh[tid], e_sh[tid + 32]),
                        fmaxf(e_sh[tid + 64], e_sh[tid + 96]));
#pragma unroll
        for (int o = 16; o > 0; o >>= 1) m = fmaxf(m, __shfl_xor_sync(0xffffffffu, m, o));
        if (tid == 0) red_sh[0] = m;
    }
    __syncthreads();
    const float mx = red_sh[0];
    if (tid < TT) e_sh[tid] = __expf(e_sh[tid] - mx);
    __syncthreads();
    if (tid < 32) {
        float ssum = e_sh[tid] + e_sh[tid + 32] + e_sh[tid + 64] + e_sh[tid + 96];
#pragma unroll
        for (int o = 16; o > 0; o >>= 1) ssum += __shfl_xor_sync(0xffffffffu, ssum, o);
        if (tid == 0) red_sh[1] = 1.f / ssum;
    }
    __syncthreads();
    const float inv = red_sh[1];

    // context: ctx[i] = inv * sum_t alpha[t] * H[b,t,i]
    for (int i = tid; i < II; i += 256) {
        const float* Hb = batch_H + (size_t)b * TT * II + i;
        float acc = 0.f;
#pragma unroll 8
        for (int t = 0; t < TT; ++t)
            acc = fmaf(e_sh[t], Hb[(size_t)t * II], acc);
        ctx[b * II + i] = acc * inv;
    }
}

// ---------------- LSTM cell elementwise ----------------
__global__ __launch_bounds__(256)
void lstm_kernel(const float* __restrict__ gates, const float* __restrict__ WohT,
                 const int* __restrict__ text, int s,
                 float* __restrict__ h, float* __restrict__ c,
                 float* __restrict__ outh)
{
    const int idx = blockIdx.x * blockDim.x + threadIdx.x;   // 0 .. B*H-1
    const int b = idx >> 9, hh = idx & 511;
    const int cls = text[b * SS + s];
    const float* wo = WohT + cls * G4H;
    const int base = b * G4H;

    float gi = gates[base + hh]        + wo[hh];
    float gf = gates[base + 512 + hh]  + wo[512 + hh];
    float gg = gates[base + 1024 + hh] + wo[1024 + hh];
    float go = gates[base + 1536 + hh] + wo[1536 + hh];

    float ci = c[idx];
    float ig = 1.f / (1.f + expf(-gi));
    float fg = 1.f / (1.f + expf(-gf));
    float og = 1.f / (1.f + expf(-go));
    float c2 = fg * ci + ig * tanhf(gg);
    float h2 = og * tanhf(c2);

    c[idx] = c2;
    h[idx] = h2;
    outh[((size_t)b * SS + s) * HH + hh] = h2;
}

// ---------------- host launcher ----------------
extern "C" void kernel_launch(void* const* d_in, const int* in_sizes, int n_in,
                              void* d_out, int out_size)
{
    const float* batch_H = (const float*)d_in[0];
    const int*   text    = (const int*)  d_in[1];
    const float* W_feat  = (const float*)d_in[2];
    const float* W_hid   = (const float*)d_in[3];
    const float* b_hid   = (const float*)d_in[4];
    const float* w_score = (const float*)d_in[5];
    const float* W_ih    = (const float*)d_in[6];
    const float* W_hh    = (const float*)d_in[7];
    const float* b_ih    = (const float*)d_in[8];
    const float* b_hh    = (const float*)d_in[9];
    const float* W_gen   = (const float*)d_in[10];
    const float* b_gen   = (const float*)d_in[11];
    float* out = (float*)d_out;

    float *feat, *h, *c, *hp, *ctx, *gates, *outh, *Wx, *WohT, *bg;
    cudaGetSymbolAddress((void**)&feat,  g_feat);
    cudaGetSymbolAddress((void**)&h,     g_h);
    cudaGetSymbolAddress((void**)&c,     g_c);
    cudaGetSymbolAddress((void**)&hp,    g_hp);
    cudaGetSymbolAddress((void**)&ctx,   g_ctx);
    cudaGetSymbolAddress((void**)&gates, g_gates);
    cudaGetSymbolAddress((void**)&outh,  g_outh);
    cudaGetSymbolAddress((void**)&Wx,    g_Wx);
    cudaGetSymbolAddress((void**)&WohT,  g_WohT);
    cudaGetSymbolAddress((void**)&bg,    g_bg);

    // pack weights + zero state (every call: graph replays must be deterministic)
    pack_kernel<<<512, 256>>>(W_ih, b_ih, b_hh);

    // feat[BT, H] = batch_H[BT, I] @ W_feat[H, I]^T
    gemm_tn<128, 128, 8, 8><<<dim3((BB * TT) / 128, HH / 128), 256>>>(
        batch_H, W_feat, nullptr, feat, BB * TT, HH, II, HH, 0);

    for (int s = 0; s < SS; ++s) {
        // hp = h @ W_hid^T + b_hid
        gemm_tn<64, 64, 4, 4><<<dim3(BB / 64, HH / 64), 256>>>(
            h, W_hid, b_hid, hp, BB, HH, HH, HH, 0);

        // attention: energies + softmax + context
        att_kernel<<<BB, 256>>>(batch_H, feat, hp, w_score, ctx);

        // gates = ctx @ Wx^T + (b_ih + b_hh)
        gemm_tn<128, 64, 8, 4><<<dim3(BB / 128, G4H / 64), 256>>>(
            ctx, Wx, bg, gates, BB, G4H, II, G4H, 0);
        // gates += h @ W_hh^T
        gemm_tn<128, 64, 8, 4><<<dim3(BB / 128, G4H / 64), 256>>>(
            h, W_hh, nullptr, gates, BB, G4H, HH, G4H, 1);

        // LSTM cell (adds one-hot column of W_ih internally)
        lstm_kernel<<<(BB * HH) / 256, 256>>>(gates, WohT, text, s, h, c, outh);
    }

    // probs[B*S, C] = outh[B*S, H] @ W_gen[C, H]^T + b_gen
    gemm_tn<64, 64, 4, 4><<<dim3((BB * SS) / 64, (CC + 63) / 64), 256>>>(
        outh, W_gen, b_gen, out, BB * SS, CC, HH, CC, 0);
}

// round 4
// speedup vs baseline: 1.9953x; 1.9953x over previous
#include <cuda_runtime.h>
#include <cuda_bf16.h>
#include <cstdint>

// Problem constants
#define BB 512
#define TT 128
#define II 512
#define HH 512
#define CC 97
#define SS 26
#define G4H 2048           // 4*H
#define NCOMB 2560         // H + 4H  (W_hid ; W_hh stacked)
#define WIH_LD 609         // I + C

// ---------------- device scratch (static, no allocs) ----------------
__device__ float g_feat[(size_t)BB * TT * HH];     // 128 MB
__device__ float g_h[BB * HH];
__device__ float g_c[BB * HH];
__device__ float g_Y[BB * NCOMB];                  // [hp | h@W_hh^T]
__device__ float g_ctx[BB * II];
__device__ float g_gates[BB * G4H];
__device__ float g_outh[(size_t)BB * SS * HH];     // 27 MB
__device__ float g_Wx[G4H * II];                   // W_ih[:, :I] packed contiguous
__device__ float g_Wcomb[NCOMB * HH];              // [W_hid ; W_hh]
__device__ float g_bcomb[NCOMB];                   // [b_hid ; 0]
__device__ float g_WohT[CC * G4H];                 // W_ih[:, I:]^T  [class][4H]
__device__ float g_bg[G4H];                        // b_ih + b_hh

// ---------------- pack / init kernel ----------------
__global__ void pack_kernel(const float* __restrict__ W_ih,
                            const float* __restrict__ b_ih,
                            const float* __restrict__ b_hh,
                            const float* __restrict__ W_hid,
                            const float* __restrict__ W_hh,
                            const float* __restrict__ b_hid)
{
    const int stride = gridDim.x * blockDim.x;
    const int t0 = blockIdx.x * blockDim.x + threadIdx.x;
    for (int i = t0; i < G4H * II; i += stride) {
        int r = i >> 9, cc = i & 511;
        g_Wx[i] = W_ih[r * WIH_LD + cc];
    }
    for (int i = t0; i < NCOMB * HH; i += stride) {
        int r = i >> 9, cc = i & 511;
        g_Wcomb[i] = (r < HH) ? W_hid[r * HH + cc] : W_hh[(r - HH) * HH + cc];
    }
    for (int i = t0; i < CC * G4H; i += stride) {
        int cls = i >> 11, j = i & 2047;
        g_WohT[i] = W_ih[j * WIH_LD + II + cls];
    }
    for (int i = t0; i < G4H; i += stride) g_bg[i] = b_ih[i] + b_hh[i];
    for (int i = t0; i < NCOMB; i += stride) g_bcomb[i] = (i < HH) ? b_hid[i] : 0.f;
    for (int i = t0; i < BB * HH; i += stride) { g_h[i] = 0.f; g_c[i] = 0.f; }
}

// ---------------- tf32 tensor-core GEMM ----------------
// C[M,N] = A[M,K] @ B[N,K]^T  (+bias[N]) (+add[row*add_ld + add_off + col])
// Requirements: K % 32 == 0, M % 64 == 0, rows of A/B 16B-aligned.
// Block: 64x64 tile, 128 threads (4 warps, 2x2 grid of 32x32 warp tiles).
__device__ __forceinline__ float cvt_tf32(float x) {
    float y;
    asm("cvt.rna.tf32.f32 %0, %1;" : "=f"(y) : "f"(x));
    return y;
}

#define MMA_TF32(d, a, b)                                                        \
    asm volatile("mma.sync.aligned.m16n8k8.row.col.f32.tf32.tf32.f32 "           \
                 "{%0,%1,%2,%3}, {%4,%5,%6,%7}, {%8,%9}, {%0,%1,%2,%3};"         \
                 : "+f"(d[0]), "+f"(d[1]), "+f"(d[2]), "+f"(d[3])                \
                 : "r"(__float_as_uint(a[0])), "r"(__float_as_uint(a[1])),       \
                   "r"(__float_as_uint(a[2])), "r"(__float_as_uint(a[3])),       \
                   "r"(__float_as_uint(b[0])), "r"(__float_as_uint(b[1])))

__global__ __launch_bounds__(128)
void gemm_tf32(const float* __restrict__ A, const float* __restrict__ B,
               const float* __restrict__ bias, const float* __restrict__ add,
               int add_ld, int add_off, float* __restrict__ C,
               int M, int N, int K, int ldc)
{
    __shared__ float As[2][64][36];
    __shared__ float Bs[2][64][36];

    const int tid  = threadIdx.x;
    const int bm   = blockIdx.x * 64;
    const int bn   = blockIdx.y * 64;
    const int w    = tid >> 5, lane = tid & 31;
    const int g    = lane >> 2, tg = lane & 3;
    const int wm   = (w & 1) * 32;
    const int wn   = (w >> 1) * 32;

    float acc[2][4][4];
#pragma unroll
    for (int mt = 0; mt < 2; ++mt)
#pragma unroll
        for (int nt = 0; nt < 4; ++nt)
#pragma unroll
            for (int r = 0; r < 4; ++r) acc[mt][nt][r] = 0.f;

    float4 stA[4], stB[4];
    const float4 z4 = make_float4(0.f, 0.f, 0.f, 0.f);
    const int nk = K >> 5;

    // ---- gmem -> regs for k-chunk ----
    auto ldg = [&](int k0) {
#pragma unroll
        for (int i = 0; i < 4; ++i) {
            int id = tid + i * 128;
            int r = id >> 3, c = (id & 7) << 2;
            stA[i] = (bm + r < M)
                   ? *reinterpret_cast<const float4*>(A + (size_t)(bm + r) * K + k0 + c) : z4;
            stB[i] = (bn + r < N)
                   ? *reinterpret_cast<const float4*>(B + (size_t)(bn + r) * K + k0 + c) : z4;
        }
    };
    // ---- regs -> smem (with tf32 rounding) ----
    auto sts = [&](int buf) {
#pragma unroll
        for (int i = 0; i < 4; ++i) {
            int id = tid + i * 128;
            int r = id >> 3, c = (id & 7) << 2;
            float4 va = make_float4(cvt_tf32(stA[i].x), cvt_tf32(stA[i].y),
                                    cvt_tf32(stA[i].z), cvt_tf32(stA[i].w));
            float4 vb = make_float4(cvt_tf32(stB[i].x), cvt_tf32(stB[i].y),
                                    cvt_tf32(stB[i].z), cvt_tf32(stB[i].w));
            *reinterpret_cast<float4*>(&As[buf][r][c]) = va;
            *reinterpret_cast<float4*>(&Bs[buf][r][c]) = vb;
        }
    };

    ldg(0);
    sts(0);
    __syncthreads();

    for (int kt = 0; kt < nk; ++kt) {
        const int buf = kt & 1;
        if (kt + 1 < nk) ldg((kt + 1) << 5);

#pragma unroll
        for (int ks = 0; ks < 4; ++ks) {
            const int kk = ks * 8;
            float a[2][4];
#pragma unroll
            for (int mt = 0; mt < 2; ++mt) {
                int r0 = wm + mt * 16 + g;
                a[mt][0] = As[buf][r0][kk + tg];
                a[mt][1] = As[buf][r0 + 8][kk + tg];
                a[mt][2] = As[buf][r0][kk + tg + 4];
                a[mt][3] = As[buf][r0 + 8][kk + tg + 4];
            }
            float bf[4][2];
#pragma unroll
            for (int nt = 0; nt < 4; ++nt) {
                int n0 = wn + nt * 8 + g;
                bf[nt][0] = Bs[buf][n0][kk + tg];
                bf[nt][1] = Bs[buf][n0][kk + tg + 4];
            }
#pragma unroll
            for (int mt = 0; mt < 2; ++mt)
#pragma unroll
                for (int nt = 0; nt < 4; ++nt)
                    MMA_TF32(acc[mt][nt], a[mt], bf[nt]);
        }

        if (kt + 1 < nk) {
            __syncthreads();
            sts((kt + 1) & 1);
        }
        __syncthreads();
    }

    // ---- epilogue ----
#pragma unroll
    for (int mt = 0; mt < 2; ++mt) {
#pragma unroll
        for (int nt = 0; nt < 4; ++nt) {
#pragma unroll
            for (int r = 0; r < 4; ++r) {
                int row = bm + wm + mt * 16 + g + ((r >> 1) << 3);
                int col = bn + wn + nt * 8 + 2 * tg + (r & 1);
                if (row < M && col < N) {
                    float v = acc[mt][nt][r];
                    if (bias) v += bias[col];
                    if (add)  v += add[(size_t)row * add_ld + add_off + col];
                    C[(size_t)row * ldc + col] = v;
                }
            }
        }
    }
}

// ---------------- fused attention: energies + softmax + context ----------------
// one block per batch row b (512 blocks, 256 threads). hp has leading dim hp_ld.
__global__ __launch_bounds__(256)
void att_kernel(const float* __restrict__ batch_H, const float* __restrict__ feat,
                const float* __restrict__ hp, int hp_ld,
                const float* __restrict__ w_score, float* __restrict__ ctx)
{
    __shared__ float hp_sh[HH];
    __shared__ float ws_sh[HH];
    __shared__ float e_sh[TT];
    __shared__ float red_sh[2];

    const int b = blockIdx.x;
    const int tid = threadIdx.x;

    hp_sh[tid]       = hp[(size_t)b * hp_ld + tid];
    hp_sh[tid + 256] = hp[(size_t)b * hp_ld + 256 + tid];
    ws_sh[tid]       = w_score[tid];
    ws_sh[tid + 256] = w_score[tid + 256];
    __syncthreads();

    const int warp = tid >> 5, lane = tid & 31;

    for (int t = warp; t < TT; t += 8) {
        const float* fr = feat + ((size_t)b * TT + t) * HH;
        float acc = 0.f;
#pragma unroll
        for (int j = 0; j < 16; ++j) {
            int hh = j * 32 + lane;
            float x = fr[hh] + hp_sh[hh];
            float th;
            asm("tanh.approx.f32 %0, %1;" : "=f"(th) : "f"(x));
            acc = fmaf(th, ws_sh[hh], acc);
        }
#pragma unroll
        for (int o = 16; o > 0; o >>= 1) acc += __shfl_xor_sync(0xffffffffu, acc, o);
        if (lane == 0) e_sh[t] = acc;
    }
    __syncthreads();

    if (tid < 32) {
        float m = fmaxf(fmaxf(e_sh[tid], e_sh[tid + 32]),
                        fmaxf(e_sh[tid + 64], e_sh[tid + 96]));
#pragma unroll
        for (int o = 16; o > 0; o >>= 1) m = fmaxf(m, __shfl_xor_sync(0xffffffffu, m, o));
        if (tid == 0) red_sh[0] = m;
    }
    __syncthreads();
    const float mx = red_sh[0];
    if (tid < TT) e_sh[tid] = __expf(e_sh[tid] - mx);
    __syncthreads();
    if (tid < 32) {
        float ssum = e_sh[tid] + e_sh[tid + 32] + e_sh[tid + 64] + e_sh[tid + 96];
#pragma unroll
        for (int o = 16; o > 0; o >>= 1) ssum += __shfl_xor_sync(0xffffffffu, ssum, o);
        if (tid == 0) red_sh[1] = 1.f / ssum;
    }
    __syncthreads();
    const float inv = red_sh[1];

    for (int i = tid; i < II; i += 256) {
        const float* Hb = batch_H + (size_t)b * TT * II + i;
        float acc = 0.f;
#pragma unroll 8
        for (int t = 0; t < TT; ++t)
            acc = fmaf(e_sh[t], Hb[(size_t)t * II], acc);
        ctx[b * II + i] = acc * inv;
    }
}

// ---------------- LSTM cell elementwise ----------------
__global__ __launch_bounds__(256)
void lstm_kernel(const float* __restrict__ gates, const float* __restrict__ WohT,
                 const int* __restrict__ text, int s,
                 float* __restrict__ h, float* __restrict__ c,
                 float* __restrict__ outh)
{
    const int idx = blockIdx.x * blockDim.x + threadIdx.x;   // 0 .. B*H-1
    const int b = idx >> 9, hh = idx & 511;
    const int cls = text[b * SS + s];
    const float* wo = WohT + cls * G4H;
    const int base = b * G4H;

    float gi = gates[base + hh]        + wo[hh];
    float gf = gates[base + 512 + hh]  + wo[512 + hh];
    float gg = gates[base + 1024 + hh] + wo[1024 + hh];
    float go = gates[base + 1536 + hh] + wo[1536 + hh];

    float ci = c[idx];
    float ig = 1.f / (1.f + expf(-gi));
    float fg = 1.f / (1.f + expf(-gf));
    float og = 1.f / (1.f + expf(-go));
    float c2 = fg * ci + ig * tanhf(gg);
    float h2 = og * tanhf(c2);

    c[idx] = c2;
    h[idx] = h2;
    outh[((size_t)b * SS + s) * HH + hh] = h2;
}

// ---------------- host launcher ----------------
extern "C" void kernel_launch(void* const* d_in, const int* in_sizes, int n_in,
                              void* d_out, int out_size)
{
    const float* batch_H = (const float*)d_in[0];
    const int*   text    = (const int*)  d_in[1];
    const float* W_feat  = (const float*)d_in[2];
    const float* W_hid   = (const float*)d_in[3];
    const float* b_hid   = (const float*)d_in[4];
    const float* w_score = (const float*)d_in[5];
    const float* W_ih    = (const float*)d_in[6];
    const float* W_hh    = (const float*)d_in[7];
    const float* b_ih    = (const float*)d_in[8];
    const float* b_hh    = (const float*)d_in[9];
    const float* W_gen   = (const float*)d_in[10];
    const float* b_gen   = (const float*)d_in[11];
    float* out = (float*)d_out;

    float *feat, *h, *c, *Y, *ctx, *gates, *outh, *Wx, *Wcomb, *bcomb, *WohT, *bg;
    cudaGetSymbolAddress((void**)&feat,  g_feat);
    cudaGetSymbolAddress((void**)&h,     g_h);
    cudaGetSymbolAddress((void**)&c,     g_c);
    cudaGetSymbolAddress((void**)&Y,     g_Y);
    cudaGetSymbolAddress((void**)&ctx,   g_ctx);
    cudaGetSymbolAddress((void**)&gates, g_gates);
    cudaGetSymbolAddress((void**)&outh,  g_outh);
    cudaGetSymbolAddress((void**)&Wx,    g_Wx);
    cudaGetSymbolAddress((void**)&Wcomb, g_Wcomb);
    cudaGetSymbolAddress((void**)&bcomb, g_bcomb);
    cudaGetSymbolAddress((void**)&WohT,  g_WohT);
    cudaGetSymbolAddress((void**)&bg,    g_bg);

    // pack weights + zero state (every call: graph replays must be deterministic)
    pack_kernel<<<512, 256>>>(W_ih, b_ih, b_hh, W_hid, W_hh, b_hid);

    // feat[BT, H] = batch_H[BT, I] @ W_feat[H, I]^T
    gemm_tf32<<<dim3((BB * TT) / 64, HH / 64), 128>>>(
        batch_H, W_feat, nullptr, nullptr, 0, 0, feat, BB * TT, HH, II, HH);

    for (int s = 0; s < SS; ++s) {
        // Y = h @ [W_hid ; W_hh]^T + [b_hid ; 0]   -> [B, 2560]
        gemm_tf32<<<dim3(BB / 64, NCOMB / 64), 128>>>(
            h, Wcomb, bcomb, nullptr, 0, 0, Y, BB, NCOMB, HH, NCOMB);

        // attention: energies + softmax + context (hp = Y[:, :512])
        att_kernel<<<BB, 256>>>(batch_H, feat, Y, NCOMB, w_score, ctx);

        // gates = ctx @ Wx^T + (b_ih + b_hh) + Y[:, 512:]
        gemm_tf32<<<dim3(BB / 64, G4H / 64), 128>>>(
            ctx, Wx, bg, Y, NCOMB, HH, gates, BB, G4H, II, G4H);

        // LSTM cell (adds one-hot column of W_ih internally)
        lstm_kernel<<<(BB * HH) / 256, 256>>>(gates, WohT, text, s, h, c, outh);
    }

    // probs[B*S, C] = outh[B*S, H] @ W_gen[C, H]^T + b_gen
    gemm_tf32<<<dim3((BB * SS) / 64, (CC + 63) / 64), 128>>>(
        outh, W_gen, b_gen, nullptr, 0, 0, out, BB * SS, CC, HH, CC);
}

// round 5
// speedup vs baseline: 2.4609x; 1.2333x over previous
#include <cuda_runtime.h>
#include <cuda_bf16.h>
#include <cuda_fp16.h>
#include <cstdint>

// Problem constants
#define BB 512
#define TT 128
#define II 512
#define HH 512
#define CC 97
#define SS 26
#define G4H 2048           // 4*H
#define NCOMB 2560         // H + 4H  (W_hid ; W_hh stacked)
#define WIH_LD 609         // I + C

// ---------------- device scratch (static, no allocs) ----------------
__device__ __half2 g_feat_h[(size_t)BB * TT * HH / 2];   // 64 MB, fp16 feat
__device__ __half2 g_H_h[(size_t)BB * TT * II / 2];      // 64 MB, fp16 batch_H
__device__ float g_h[BB * HH];
__device__ float g_c[BB * HH];
__device__ float g_Y[BB * NCOMB];                  // [hp | h@W_hh^T]
__device__ float g_ctx[BB * II];
__device__ float g_gates[BB * G4H];
__device__ float g_outh[(size_t)BB * SS * HH];     // 27 MB
__device__ float g_Wx[G4H * II];                   // W_ih[:, :I] packed contiguous
__device__ float g_Wcomb[NCOMB * HH];              // [W_hid ; W_hh]
__device__ float g_bcomb[NCOMB];                   // [b_hid ; 0]
__device__ float g_WohT[CC * G4H];                 // W_ih[:, I:]^T  [class][4H]
__device__ float g_bg[G4H];                        // b_ih + b_hh

// ---------------- pack / init kernel ----------------
__global__ void pack_kernel(const float* __restrict__ W_ih,
                            const float* __restrict__ b_ih,
                            const float* __restrict__ b_hh,
                            const float* __restrict__ W_hid,
                            const float* __restrict__ W_hh,
                            const float* __restrict__ b_hid,
                            const float* __restrict__ batch_H)
{
    const int stride = gridDim.x * blockDim.x;
    const int t0 = blockIdx.x * blockDim.x + threadIdx.x;
    for (int i = t0; i < G4H * II; i += stride) {
        int r = i >> 9, cc = i & 511;
        g_Wx[i] = W_ih[r * WIH_LD + cc];
    }
    for (int i = t0; i < NCOMB * HH; i += stride) {
        int r = i >> 9, cc = i & 511;
        g_Wcomb[i] = (r < HH) ? W_hid[r * HH + cc] : W_hh[(r - HH) * HH + cc];
    }
    for (int i = t0; i < CC * G4H; i += stride) {
        int cls = i >> 11, j = i & 2047;
        g_WohT[i] = W_ih[j * WIH_LD + II + cls];
    }
    for (int i = t0; i < G4H; i += stride) g_bg[i] = b_ih[i] + b_hh[i];
    for (int i = t0; i < NCOMB; i += stride) g_bcomb[i] = (i < HH) ? b_hid[i] : 0.f;
    for (int i = t0; i < BB * HH; i += stride) { g_h[i] = 0.f; g_c[i] = 0.f; }
    // batch_H -> fp16 (round-to-nearest)
    const size_t nh2 = (size_t)BB * TT * II / 2;
    const float2* src = reinterpret_cast<const float2*>(batch_H);
    for (size_t i = t0; i < nh2; i += stride)
        g_H_h[i] = __float22half2_rn(src[i]);
}

// ---------------- tf32 tensor-core GEMM ----------------
// C[M,N] = A[M,K] @ B[N,K]^T  (+bias[N]) (+add[row*add_ld + add_off + col])
// Output to fp32 C or (if Ch != nullptr) fp16 Ch.
// Requirements: K % 32 == 0, rows of A/B 16B-aligned.
// Block: 64x64 tile, 128 threads (4 warps, 2x2 grid of 32x32 warp tiles).
__device__ __forceinline__ float cvt_tf32(float x) {
    float y;
    asm("cvt.rna.tf32.f32 %0, %1;" : "=f"(y) : "f"(x));
    return y;
}

#define MMA_TF32(d, a, b)                                                        \
    asm volatile("mma.sync.aligned.m16n8k8.row.col.f32.tf32.tf32.f32 "           \
                 "{%0,%1,%2,%3}, {%4,%5,%6,%7}, {%8,%9}, {%0,%1,%2,%3};"         \
                 : "+f"(d[0]), "+f"(d[1]), "+f"(d[2]), "+f"(d[3])                \
                 : "r"(__float_as_uint(a[0])), "r"(__float_as_uint(a[1])),       \
                   "r"(__float_as_uint(a[2])), "r"(__float_as_uint(a[3])),       \
                   "r"(__float_as_uint(b[0])), "r"(__float_as_uint(b[1])))

__global__ __launch_bounds__(128)
void gemm_tf32(const float* __restrict__ A, const float* __restrict__ B,
               const float* __restrict__ bias, const float* __restrict__ add,
               int add_ld, int add_off, float* __restrict__ C,
               __half* __restrict__ Ch,
               int M, int N, int K, int ldc)
{
    __shared__ float As[2][64][36];
    __shared__ float Bs[2][64][36];

    const int tid  = threadIdx.x;
    const int bm   = blockIdx.x * 64;
    const int bn   = blockIdx.y * 64;
    const int w    = tid >> 5, lane = tid & 31;
    const int g    = lane >> 2, tg = lane & 3;
    const int wm   = (w & 1) * 32;
    const int wn   = (w >> 1) * 32;

    float acc[2][4][4];
#pragma unroll
    for (int mt = 0; mt < 2; ++mt)
#pragma unroll
        for (int nt = 0; nt < 4; ++nt)
#pragma unroll
            for (int r = 0; r < 4; ++r) acc[mt][nt][r] = 0.f;

    float4 stA[4], stB[4];
    const float4 z4 = make_float4(0.f, 0.f, 0.f, 0.f);
    const int nk = K >> 5;

    auto ldg = [&](int k0) {
#pragma unroll
        for (int i = 0; i < 4; ++i) {
            int id = tid + i * 128;
            int r = id >> 3, c = (id & 7) << 2;
            stA[i] = (bm + r < M)
                   ? *reinterpret_cast<const float4*>(A + (size_t)(bm + r) * K + k0 + c) : z4;
            stB[i] = (bn + r < N)
                   ? *reinterpret_cast<const float4*>(B + (size_t)(bn + r) * K + k0 + c) : z4;
        }
    };
    auto sts = [&](int buf) {
#pragma unroll
        for (int i = 0; i < 4; ++i) {
            int id = tid + i * 128;
            int r = id >> 3, c = (id & 7) << 2;
            float4 va = make_float4(cvt_tf32(stA[i].x), cvt_tf32(stA[i].y),
                                    cvt_tf32(stA[i].z), cvt_tf32(stA[i].w));
            float4 vb = make_float4(cvt_tf32(stB[i].x), cvt_tf32(stB[i].y),
                                    cvt_tf32(stB[i].z), cvt_tf32(stB[i].w));
            *reinterpret_cast<float4*>(&As[buf][r][c]) = va;
            *reinterpret_cast<float4*>(&Bs[buf][r][c]) = vb;
        }
    };

    ldg(0);
    sts(0);
    __syncthreads();

    for (int kt = 0; kt < nk; ++kt) {
        const int buf = kt & 1;
        if (kt + 1 < nk) ldg((kt + 1) << 5);

#pragma unroll
        for (int ks = 0; ks < 4; ++ks) {
            const int kk = ks * 8;
            float a[2][4];
#pragma unroll
            for (int mt = 0; mt < 2; ++mt) {
                int r0 = wm + mt * 16 + g;
                a[mt][0] = As[buf][r0][kk + tg];
                a[mt][1] = As[buf][r0 + 8][kk + tg];
                a[mt][2] = As[buf][r0][kk + tg + 4];
                a[mt][3] = As[buf][r0 + 8][kk + tg + 4];
            }
            float bf[4][2];
#pragma unroll
            for (int nt = 0; nt < 4; ++nt) {
                int n0 = wn + nt * 8 + g;
                bf[nt][0] = Bs[buf][n0][kk + tg];
                bf[nt][1] = Bs[buf][n0][kk + tg + 4];
            }
#pragma unroll
            for (int mt = 0; mt < 2; ++mt)
#pragma unroll
                for (int nt = 0; nt < 4; ++nt)
                    MMA_TF32(acc[mt][nt], a[mt], bf[nt]);
        }

        if (kt + 1 < nk) {
            __syncthreads();
            sts((kt + 1) & 1);
        }
        __syncthreads();
    }

    // ---- epilogue ----
#pragma unroll
    for (int mt = 0; mt < 2; ++mt) {
#pragma unroll
        for (int nt = 0; nt < 4; ++nt) {
#pragma unroll
            for (int r = 0; r < 4; ++r) {
                int row = bm + wm + mt * 16 + g + ((r >> 1) << 3);
                int col = bn + wn + nt * 8 + 2 * tg + (r & 1);
                if (row < M && col < N) {
                    float v = acc[mt][nt][r];
                    if (bias) v += bias[col];
                    if (add)  v += add[(size_t)row * add_ld + add_off + col];
                    if (Ch) Ch[(size_t)row * ldc + col] = __float2half_rn(v);
                    else    C [(size_t)row * ldc + col] = v;
                }
            }
        }
    }
}

// ---------------- fused attention (fp16 feat / batch_H) ----------------
// one block per batch row b (512 blocks, 256 threads). hp has leading dim hp_ld.
__global__ __launch_bounds__(256)
void att_kernel(const __half2* __restrict__ H2, const __half2* __restrict__ F2,
                const float* __restrict__ hp, int hp_ld,
                const float* __restrict__ w_score, float* __restrict__ ctx)
{
    __shared__ float2 hp_sh[HH / 2];
    __shared__ float2 ws_sh[HH / 2];
    __shared__ float e_sh[TT];
    __shared__ float red_sh[2];

    const int b = blockIdx.x;
    const int tid = threadIdx.x;

    // load hp, w_score into float2-banked smem
    {
        const float2* hp2 = reinterpret_cast<const float2*>(hp + (size_t)b * hp_ld);
        const float2* ws2 = reinterpret_cast<const float2*>(w_score);
        hp_sh[tid] = hp2[tid];
        ws_sh[tid] = ws2[tid];
    }
    __syncthreads();

    const int warp = tid >> 5, lane = tid & 31;

    // energies: e[t] = sum_h tanh(feat + hp) * w   (H=512 -> 256 half2)
    for (int t = warp; t < TT; t += 8) {
        const __half2* fr = F2 + ((size_t)b * TT + t) * (HH / 2);
        float acc = 0.f;
#pragma unroll
        for (int j = 0; j < 8; ++j) {
            int idx = j * 32 + lane;
            float2 f = __half22float2(fr[idx]);
            float2 hv = hp_sh[idx];
            float2 wv = ws_sh[idx];
            float t0, t1;
            asm("tanh.approx.f32 %0, %1;" : "=f"(t0) : "f"(f.x + hv.x));
            asm("tanh.approx.f32 %0, %1;" : "=f"(t1) : "f"(f.y + hv.y));
            acc = fmaf(t0, wv.x, fmaf(t1, wv.y, acc));
        }
#pragma unroll
        for (int o = 16; o > 0; o >>= 1) acc += __shfl_xor_sync(0xffffffffu, acc, o);
        if (lane == 0) e_sh[t] = acc;
    }
    __syncthreads();

    // softmax over T=128
    if (tid < 32) {
        float m = fmaxf(fmaxf(e_sh[tid], e_sh[tid + 32]),
                        fmaxf(e_sh[tid + 64], e_sh[tid + 96]));
#pragma unroll
        for (int o = 16; o > 0; o >>= 1) m = fmaxf(m, __shfl_xor_sync(0xffffffffu, m, o));
        if (tid == 0) red_sh[0] = m;
    }
    __syncthreads();
    const float mx = red_sh[0];
    if (tid < TT) e_sh[tid] = __expf(e_sh[tid] - mx);
    __syncthreads();
    if (tid < 32) {
        float ssum = e_sh[tid] + e_sh[tid + 32] + e_sh[tid + 64] + e_sh[tid + 96];
#pragma unroll
        for (int o = 16; o > 0; o >>= 1) ssum += __shfl_xor_sync(0xffffffffu, ssum, o);
        if (tid == 0) red_sh[1] = 1.f / ssum;
    }
    __syncthreads();
    const float inv = red_sh[1];

    // context: ctx[:, 2*tid .. 2*tid+1] = inv * sum_t alpha[t] * H[b,t,:]
    {
        const __half2* Hb = H2 + (size_t)b * TT * (II / 2) + tid;
        float accx = 0.f, accy = 0.f;
#pragma unroll 8
        for (int t = 0; t < TT; ++t) {
            float2 v = __half22float2(Hb[(size_t)t * (II / 2)]);
            float a = e_sh[t];
            accx = fmaf(a, v.x, accx);
            accy = fmaf(a, v.y, accy);
        }
        float2* c2 = reinterpret_cast<float2*>(ctx + (size_t)b * II);
        c2[tid] = make_float2(accx * inv, accy * inv);
    }
}

// ---------------- LSTM cell elementwise ----------------
__global__ __launch_bounds__(256)
void lstm_kernel(const float* __restrict__ gates, const float* __restrict__ WohT,
                 const int* __restrict__ text, int s,
                 float* __restrict__ h, float* __restrict__ c,
                 float* __restrict__ outh)
{
    const int idx = blockIdx.x * blockDim.x + threadIdx.x;   // 0 .. B*H-1
    const int b = idx >> 9, hh = idx & 511;
    const int cls = text[b * SS + s];
    const float* wo = WohT + cls * G4H;
    const int base = b * G4H;

    float gi = gates[base + hh]        + wo[hh];
    float gf = gates[base + 512 + hh]  + wo[512 + hh];
    float gg = gates[base + 1024 + hh] + wo[1024 + hh];
    float go = gates[base + 1536 + hh] + wo[1536 + hh];

    float ci = c[idx];
    float ig = 1.f / (1.f + expf(-gi));
    float fg = 1.f / (1.f + expf(-gf));
    float og = 1.f / (1.f + expf(-go));
    float c2 = fg * ci + ig * tanhf(gg);
    float h2 = og * tanhf(c2);

    c[idx] = c2;
    h[idx] = h2;
    outh[((size_t)b * SS + s) * HH + hh] = h2;
}

// ---------------- host launcher ----------------
extern "C" void kernel_launch(void* const* d_in, const int* in_sizes, int n_in,
                              void* d_out, int out_size)
{
    const float* batch_H = (const float*)d_in[0];
    const int*   text    = (const int*)  d_in[1];
    const float* W_feat  = (const float*)d_in[2];
    const float* W_hid   = (const float*)d_in[3];
    const float* b_hid   = (const float*)d_in[4];
    const float* w_score = (const float*)d_in[5];
    const float* W_ih    = (const float*)d_in[6];
    const float* W_hh    = (const float*)d_in[7];
    const float* b_ih    = (const float*)d_in[8];
    const float* b_hh    = (const float*)d_in[9];
    const float* W_gen   = (const float*)d_in[10];
    const float* b_gen   = (const float*)d_in[11];
    float* out = (float*)d_out;

    float *h, *c, *Y, *ctx, *gates, *outh, *Wx, *Wcomb, *bcomb, *WohT, *bg;
    __half2 *feat_h, *H_h;
    cudaGetSymbolAddress((void**)&feat_h, g_feat_h);
    cudaGetSymbolAddress((void**)&H_h,    g_H_h);
    cudaGetSymbolAddress((void**)&h,     g_h);
    cudaGetSymbolAddress((void**)&c,     g_c);
    cudaGetSymbolAddress((void**)&Y,     g_Y);
    cudaGetSymbolAddress((void**)&ctx,   g_ctx);
    cudaGetSymbolAddress((void**)&gates, g_gates);
    cudaGetSymbolAddress((void**)&outh,  g_outh);
    cudaGetSymbolAddress((void**)&Wx,    g_Wx);
    cudaGetSymbolAddress((void**)&Wcomb, g_Wcomb);
    cudaGetSymbolAddress((void**)&bcomb, g_bcomb);
    cudaGetSymbolAddress((void**)&WohT,  g_WohT);
    cudaGetSymbolAddress((void**)&bg,    g_bg);

    // pack weights + fp16 batch_H + zero state
    pack_kernel<<<512, 256>>>(W_ih, b_ih, b_hh, W_hid, W_hh, b_hid, batch_H);

    // feat[BT, H] = batch_H[BT, I] @ W_feat[H, I]^T  -> fp16
    gemm_tf32<<<dim3((BB * TT) / 64, HH / 64), 128>>>(
        batch_H, W_feat, nullptr, nullptr, 0, 0,
        nullptr, (__half*)feat_h, BB * TT, HH, II, HH);

    for (int s = 0; s < SS; ++s) {
        // Y = h @ [W_hid ; W_hh]^T + [b_hid ; 0]   -> [B, 2560]
        gemm_tf32<<<dim3(BB / 64, NCOMB / 64), 128>>>(
            h, Wcomb, bcomb, nullptr, 0, 0, Y, nullptr, BB, NCOMB, HH, NCOMB);

        // attention: energies + softmax + context (hp = Y[:, :512])
        att_kernel<<<BB, 256>>>(H_h, feat_h, Y, NCOMB, w_score, ctx);

        // gates = ctx @ Wx^T + (b_ih + b_hh) + Y[:, 512:]
        gemm_tf32<<<dim3(BB / 64, G4H / 64), 128>>>(
            ctx, Wx, bg, Y, NCOMB, HH, gates, nullptr, BB, G4H, II, G4H);

        // LSTM cell (adds one-hot column of W_ih internally)
        lstm_kernel<<<(BB * HH) / 256, 256>>>(gates, WohT, text, s, h, c, outh);
    }

    // probs[B*S, C] = outh[B*S, H] @ W_gen[C, H]^T + b_gen
    gemm_tf32<<<dim3((BB * SS) / 64, (CC + 63) / 64), 128>>>(
        outh, W_gen, b_gen, nullptr, 0, 0, out, nullptr, BB * SS, CC, HH, CC);
}

// round 6
// speedup vs baseline: 3.2050x; 1.3024x over previous
#include <cuda_runtime.h>
#include <cuda_bf16.h>
#include <cuda_fp16.h>
#include <cstdint>

// Problem constants
#define BB 512
#define TT 128
#define II 512
#define HH 512
#define CC 97
#define SS 26
#define G4H 2048           // 4*H
#define NCOMB 2560         // H + 4H  (W_hid ; W_hh stacked)
#define WIH_LD 609         // I + C

// ---------------- device scratch (static, no allocs) ----------------
__device__ __half2 g_feat_h[(size_t)BB * TT * HH / 2];   // 64 MB fp16 feat
__device__ __half2 g_H_h[(size_t)BB * TT * II / 2];      // 64 MB fp16 batch_H
__device__ __half  g_h_h[BB * HH];                       // fp16 hidden state
__device__ float   g_c[BB * HH];
__device__ float   g_Y[BB * NCOMB];                      // [hp | h@W_hh^T]  fp32
__device__ __half2 g_ctx_h[BB * II / 2];                 // fp16 context
__device__ float   g_gates[BB * G4H];
__device__ __half  g_outh_h[(size_t)BB * SS * HH];       // fp16 step outputs
__device__ __half  g_Wx_h[G4H * II];                     // W_ih[:, :I] fp16
__device__ __half  g_Wcomb_h[NCOMB * HH];                // [W_hid ; W_hh] fp16
__device__ __half  g_Wfeat_h[HH * II];
__device__ __half  g_Wgen_h[CC * HH];
__device__ float   g_bcomb[NCOMB];                       // [b_hid ; 0]
__device__ float   g_WohT[CC * G4H];                     // W_ih[:, I:]^T
__device__ float   g_bg[G4H];                            // b_ih + b_hh

// ---------------- pack / init kernel ----------------
__global__ void pack_kernel(const float* __restrict__ W_ih,
                            const float* __restrict__ b_ih,
                            const float* __restrict__ b_hh,
                            const float* __restrict__ W_hid,
                            const float* __restrict__ W_hh,
                            const float* __restrict__ b_hid,
                            const float* __restrict__ W_feat,
                            const float* __restrict__ W_gen,
                            const float* __restrict__ batch_H)
{
    const int stride = gridDim.x * blockDim.x;
    const int t0 = blockIdx.x * blockDim.x + threadIdx.x;
    for (int i = t0; i < G4H * II; i += stride) {
        int r = i >> 9, cc = i & 511;
        g_Wx_h[i] = __float2half_rn(W_ih[r * WIH_LD + cc]);
    }
    for (int i = t0; i < NCOMB * HH; i += stride) {
        int r = i >> 9, cc = i & 511;
        g_Wcomb_h[i] = __float2half_rn((r < HH) ? W_hid[r * HH + cc]
                                                : W_hh[(r - HH) * HH + cc]);
    }
    for (int i = t0; i < HH * II; i += stride)
        g_Wfeat_h[i] = __float2half_rn(W_feat[i]);
    for (int i = t0; i < CC * HH; i += stride)
        g_Wgen_h[i] = __float2half_rn(W_gen[i]);
    for (int i = t0; i < CC * G4H; i += stride) {
        int cls = i >> 11, j = i & 2047;
        g_WohT[i] = W_ih[j * WIH_LD + II + cls];
    }
    for (int i = t0; i < G4H; i += stride) g_bg[i] = b_ih[i] + b_hh[i];
    for (int i = t0; i < NCOMB; i += stride) g_bcomb[i] = (i < HH) ? b_hid[i] : 0.f;
    for (int i = t0; i < BB * HH; i += stride) {
        g_h_h[i] = __float2half_rn(0.f);
        g_c[i] = 0.f;
    }
    const size_t nh2 = (size_t)BB * TT * II / 2;
    const float2* src = reinterpret_cast<const float2*>(batch_H);
    for (size_t i = t0; i < nh2; i += stride)
        g_H_h[i] = __float22half2_rn(src[i]);
}

// ---------------- fp16 tensor-core GEMM ----------------
// C[M,N] = A[M,K] @ B[N,K]^T  (+bias[N]) (+add[row*add_ld+add_off+col])
// A,B fp16 row-major (ld == K, K % 32 == 0). Out fp32 C or fp16 Ch.
// Block: 64x64 tile, 128 threads (4 warps, 2x2 of 32x32 warp tiles), BK=32.
#define SMP 56   // smem row pitch in halfs (112B: 16B-aligned, conflict-free frags)

#define MMA_F16(d, a, b)                                                         \
    asm volatile("mma.sync.aligned.m16n8k16.row.col.f32.f16.f16.f32 "            \
                 "{%0,%1,%2,%3}, {%4,%5,%6,%7}, {%8,%9}, {%0,%1,%2,%3};"         \
                 : "+f"(d[0]), "+f"(d[1]), "+f"(d[2]), "+f"(d[3])                \
                 : "r"(a[0]), "r"(a[1]), "r"(a[2]), "r"(a[3]),                   \
                   "r"(b[0]), "r"(b[1]))

__global__ __launch_bounds__(128)
void gemm_f16(const __half* __restrict__ A, const __half* __restrict__ B,
              const float* __restrict__ bias, const float* __restrict__ add,
              int add_ld, int add_off, float* __restrict__ C,
              __half* __restrict__ Ch,
              int M, int N, int K, int ldc)
{
    __shared__ __half As[2][64][SMP];
    __shared__ __half Bs[2][64][SMP];

    const int tid  = threadIdx.x;
    const int bm   = blockIdx.x * 64;
    const int bn   = blockIdx.y * 64;
    const int w    = tid >> 5, lane = tid & 31;
    const int g    = lane >> 2, tg = lane & 3;
    const int wm   = (w & 1) * 32;
    const int wn   = (w >> 1) * 32;

    float acc[2][4][4];
#pragma unroll
    for (int mt = 0; mt < 2; ++mt)
#pragma unroll
        for (int nt = 0; nt < 4; ++nt)
#pragma unroll
            for (int r = 0; r < 4; ++r) acc[mt][nt][r] = 0.f;

    uint4 stA[2], stB[2];
    const uint4 z4 = make_uint4(0u, 0u, 0u, 0u);
    const int nk = K >> 5;
    const int kld = K >> 3;   // uint4 per row

    auto ldg = [&](int k0) {
#pragma unroll
        for (int i = 0; i < 2; ++i) {
            int id = tid + i * 128;
            int r = id >> 2, cg = id & 3;
            const uint4* Ar = reinterpret_cast<const uint4*>(A) + (size_t)(bm + r) * kld + (k0 >> 3) + cg;
            const uint4* Br = reinterpret_cast<const uint4*>(B) + (size_t)(bn + r) * kld + (k0 >> 3) + cg;
            stA[i] = (bm + r < M) ? *Ar : z4;
            stB[i] = (bn + r < N) ? *Br : z4;
        }
    };
    auto sts = [&](int buf) {
#pragma unroll
        for (int i = 0; i < 2; ++i) {
            int id = tid + i * 128;
            int r = id >> 2, cg = id & 3;
            *reinterpret_cast<uint4*>(&As[buf][r][cg * 8]) = stA[i];
            *reinterpret_cast<uint4*>(&Bs[buf][r][cg * 8]) = stB[i];
        }
    };

    ldg(0);
    sts(0);
    __syncthreads();

    for (int kt = 0; kt < nk; ++kt) {
        const int buf = kt & 1;
        if (kt + 1 < nk) ldg((kt + 1) << 5);

#pragma unroll
        for (int ks = 0; ks < 32; ks += 16) {
            unsigned a[2][4];
#pragma unroll
            for (int mt = 0; mt < 2; ++mt) {
                int r0 = wm + mt * 16 + g;
                a[mt][0] = *reinterpret_cast<const unsigned*>(&As[buf][r0][ks + 2 * tg]);
                a[mt][1] = *reinterpret_cast<const unsigned*>(&As[buf][r0 + 8][ks + 2 * tg]);
                a[mt][2] = *reinterpret_cast<const unsigned*>(&As[buf][r0][ks + 8 + 2 * tg]);
                a[mt][3] = *reinterpret_cast<const unsigned*>(&As[buf][r0 + 8][ks + 8 + 2 * tg]);
            }
            unsigned bf[4][2];
#pragma unroll
            for (int nt = 0; nt < 4; ++nt) {
                int n0 = wn + nt * 8 + g;
                bf[nt][0] = *reinterpret_cast<const unsigned*>(&Bs[buf][n0][ks + 2 * tg]);
                bf[nt][1] = *reinterpret_cast<const unsigned*>(&Bs[buf][n0][ks + 8 + 2 * tg]);
            }
#pragma unroll
            for (int mt = 0; mt < 2; ++mt)
#pragma unroll
                for (int nt = 0; nt < 4; ++nt)
                    MMA_F16(acc[mt][nt], a[mt], bf[nt]);
        }

        if (kt + 1 < nk) {
            __syncthreads();
            sts((kt + 1) & 1);
        }
        __syncthreads();
    }

    // ---- epilogue ----
#pragma unroll
    for (int mt = 0; mt < 2; ++mt) {
#pragma unroll
        for (int nt = 0; nt < 4; ++nt) {
#pragma unroll
            for (int r = 0; r < 4; ++r) {
                int row = bm + wm + mt * 16 + g + ((r >> 1) << 3);
                int col = bn + wn + nt * 8 + 2 * tg + (r & 1);
                if (row < M && col < N) {
                    float v = acc[mt][nt][r];
                    if (bias) v += bias[col];
                    if (add)  v += add[(size_t)row * add_ld + add_off + col];
                    if (Ch) Ch[(size_t)row * ldc + col] = __float2half_rn(v);
                    else    C [(size_t)row * ldc + col] = v;
                }
            }
        }
    }
}

// ---------------- fused attention (fp16 feat / batch_H, uint4 loads) ----------------
// one block per batch row b (512 blocks, 256 threads). hp fp32 with leading dim hp_ld.
__global__ __launch_bounds__(256)
void att_kernel(const uint4* __restrict__ H4, const uint4* __restrict__ F4,
                const float* __restrict__ hp, int hp_ld,
                const float* __restrict__ w_score, __half2* __restrict__ ctx)
{
    __shared__ float e_sh[TT];
    __shared__ float red_sh[2];
    __shared__ float red4[4][64][8];

    const int b = blockIdx.x;
    const int tid = threadIdx.x;
    const int warp = tid >> 5, lane = tid & 31;

    // per-lane register cache of hp and w_score (fixed 8 half2-indices per lane)
    float2 hpv[8], wsv[8];
    {
        const float2* hp2 = reinterpret_cast<const float2*>(hp + (size_t)b * hp_ld);
        const float2* ws2 = reinterpret_cast<const float2*>(w_score);
#pragma unroll
        for (int j = 0; j < 2; ++j)
#pragma unroll
            for (int q = 0; q < 4; ++q) {
                int idx = 4 * (j * 32 + lane) + q;
                hpv[j * 4 + q] = hp2[idx];
                wsv[j * 4 + q] = ws2[idx];
            }
    }

    // energies: e[t] = sum_h tanh(feat+hp)*w ; two t per iteration
    for (int t0 = warp; t0 < TT; t0 += 16) {
        const int t1 = t0 + 8;
        const uint4* f0 = F4 + ((size_t)b * TT + t0) * 64;
        const uint4* f1 = F4 + ((size_t)b * TT + t1) * 64;
        uint4 u0a = f0[lane], u0b = f0[32 + lane];
        uint4 u1a = f1[lane], u1b = f1[32 + lane];
        float acc0 = 0.f, acc1 = 0.f;
#pragma unroll
        for (int q = 0; q < 4; ++q) {
            {
                float2 f = __half22float2(reinterpret_cast<const __half2*>(&u0a)[q]);
                float2 hv = hpv[q], wv = wsv[q];
                float a0, a1;
                asm("tanh.approx.f32 %0, %1;" : "=f"(a0) : "f"(f.x + hv.x));
                asm("tanh.approx.f32 %0, %1;" : "=f"(a1) : "f"(f.y + hv.y));
                acc0 = fmaf(a0, wv.x, fmaf(a1, wv.y, acc0));
            }
            {
                float2 f = __half22float2(reinterpret_cast<const __half2*>(&u0b)[q]);
                float2 hv = hpv[4 + q], wv = wsv[4 + q];
                float a0, a1;
                asm("tanh.approx.f32 %0, %1;" : "=f"(a0) : "f"(f.x + hv.x));
                asm("tanh.approx.f32 %0, %1;" : "=f"(a1) : "f"(f.y + hv.y));
                acc0 = fmaf(a0, wv.x, fmaf(a1, wv.y, acc0));
            }
            {
                float2 f = __half22float2(reinterpret_cast<const __half2*>(&u1a)[q]);
                float2 hv = hpv[q], wv = wsv[q];
                float a0, a1;
                asm("tanh.approx.f32 %0, %1;" : "=f"(a0) : "f"(f.x + hv.x));
                asm("tanh.approx.f32 %0, %1;" : "=f"(a1) : "f"(f.y + hv.y));
                acc1 = fmaf(a0, wv.x, fmaf(a1, wv.y, acc1));
            }
            {
                float2 f = __half22float2(reinterpret_cast<const __half2*>(&u1b)[q]);
                float2 hv = hpv[4 + q], wv = wsv[4 + q];
                float a0, a1;
                asm("tanh.approx.f32 %0, %1;" : "=f"(a0) : "f"(f.x + hv.x));
                asm("tanh.approx.f32 %0, %1;" : "=f"(a1) : "f"(f.y + hv.y));
                acc1 = fmaf(a0, wv.x, fmaf(a1, wv.y, acc1));
            }
        }
#pragma unroll
        for (int o = 16; o > 0; o >>= 1) {
            acc0 += __shfl_xor_sync(0xffffffffu, acc0, o);
            acc1 += __shfl_xor_sync(0xffffffffu, acc1, o);
        }
        if (lane == 0) { e_sh[t0] = acc0; e_sh[t1] = acc1; }
    }
    __syncthreads();

    // softmax over T=128
    if (tid < 32) {
        float m = fmaxf(fmaxf(e_sh[tid], e_sh[tid + 32]),
                        fmaxf(e_sh[tid + 64], e_sh[tid + 96]));
#pragma unroll
        for (int o = 16; o > 0; o >>= 1) m = fmaxf(m, __shfl_xor_sync(0xffffffffu, m, o));
        if (tid == 0) red_sh[0] = m;
    }
    __syncthreads();
    const float mx = red_sh[0];
    if (tid < TT) e_sh[tid] = __expf(e_sh[tid] - mx);
    __syncthreads();
    if (tid < 32) {
        float ssum = e_sh[tid] + e_sh[tid + 32] + e_sh[tid + 64] + e_sh[tid + 96];
#pragma unroll
        for (int o = 16; o > 0; o >>= 1) ssum += __shfl_xor_sync(0xffffffffu, ssum, o);
        if (tid == 0) red_sh[1] = 1.f / ssum;
    }
    __syncthreads();

    // context: 4 t-groups x 64 threads, 8 floats (1 uint4 of halfs) per thread
    {
        const int tg4 = tid >> 6, ti = tid & 63;
        const uint4* Hb = H4 + (size_t)b * TT * 64 + ti;
        float acc[8];
#pragma unroll
        for (int q = 0; q < 8; ++q) acc[q] = 0.f;
        const int tbeg = tg4 * 32;
#pragma unroll 4
        for (int t = tbeg; t < tbeg + 32; ++t) {
            uint4 u = Hb[(size_t)t * 64];
            float a = e_sh[t];
#pragma unroll
            for (int q = 0; q < 4; ++q) {
                float2 v = __half22float2(reinterpret_cast<const __half2*>(&u)[q]);
                acc[2 * q]     = fmaf(a, v.x, acc[2 * q]);
                acc[2 * q + 1] = fmaf(a, v.y, acc[2 * q + 1]);
            }
        }
#pragma unroll
        for (int q = 0; q < 8; ++q) red4[tg4][ti][q] = acc[q];
    }
    __syncthreads();

    if (tid < 64) {
        const float inv = red_sh[1];
        __half2 o4[4];
#pragma unroll
        for (int q = 0; q < 4; ++q) {
            float x = (red4[0][tid][2*q]   + red4[1][tid][2*q] +
                       red4[2][tid][2*q]   + red4[3][tid][2*q]) * inv;
            float y = (red4[0][tid][2*q+1] + red4[1][tid][2*q+1] +
                       red4[2][tid][2*q+1] + red4[3][tid][2*q+1]) * inv;
            o4[q] = __float22half2_rn(make_float2(x, y));
        }
        *reinterpret_cast<uint4*>(&ctx[(size_t)b * (II / 2) + tid * 4]) =
            *reinterpret_cast<const uint4*>(o4);
    }
}

// ---------------- LSTM cell elementwise ----------------
__global__ __launch_bounds__(256)
void lstm_kernel(const float* __restrict__ gates, const float* __restrict__ WohT,
                 const int* __restrict__ text, int s,
                 __half* __restrict__ h_h, float* __restrict__ c,
                 __half* __restrict__ outh_h)
{
    const int idx = blockIdx.x * blockDim.x + threadIdx.x;   // 0 .. B*H-1
    const int b = idx >> 9, hh = idx & 511;
    const int cls = text[b * SS + s];
    const float* wo = WohT + cls * G4H;
    const int base = b * G4H;

    float gi = gates[base + hh]        + wo[hh];
    float gf = gates[base + 512 + hh]  + wo[512 + hh];
    float gg = gates[base + 1024 + hh] + wo[1024 + hh];
    float go = gates[base + 1536 + hh] + wo[1536 + hh];

    float ci = c[idx];
    float ig = 1.f / (1.f + expf(-gi));
    float fg = 1.f / (1.f + expf(-gf));
    float og = 1.f / (1.f + expf(-go));
    float c2 = fg * ci + ig * tanhf(gg);
    float h2 = og * tanhf(c2);

    c[idx] = c2;
    h_h[idx] = __float2half_rn(h2);
    outh_h[((size_t)b * SS + s) * HH + hh] = __float2half_rn(h2);
}

// ---------------- host launcher ----------------
extern "C" void kernel_launch(void* const* d_in, const int* in_sizes, int n_in,
                              void* d_out, int out_size)
{
    const float* batch_H = (const float*)d_in[0];
    const int*   text    = (const int*)  d_in[1];
    const float* W_feat  = (const float*)d_in[2];
    const float* W_hid   = (const float*)d_in[3];
    const float* b_hid   = (const float*)d_in[4];
    const float* w_score = (const float*)d_in[5];
    const float* W_ih    = (const float*)d_in[6];
    const float* W_hh    = (const float*)d_in[7];
    const float* b_ih    = (const float*)d_in[8];
    const float* b_hh    = (const float*)d_in[9];
    const float* W_gen   = (const float*)d_in[10];
    const float* b_gen   = (const float*)d_in[11];
    float* out = (float*)d_out;

    float *c, *Y, *gates, *bcomb, *WohT, *bg;
    __half2 *feat_h, *H_h, *ctx_h;
    __half *h_h, *outh_h, *Wx_h, *Wcomb_h, *Wfeat_h, *Wgen_h;
    cudaGetSymbolAddress((void**)&feat_h,  g_feat_h);
    cudaGetSymbolAddress((void**)&H_h,     g_H_h);
    cudaGetSymbolAddress((void**)&h_h,     g_h_h);
    cudaGetSymbolAddress((void**)&c,       g_c);
    cudaGetSymbolAddress((void**)&Y,       g_Y);
    cudaGetSymbolAddress((void**)&ctx_h,   g_ctx_h);
    cudaGetSymbolAddress((void**)&gates,   g_gates);
    cudaGetSymbolAddress((void**)&outh_h,  g_outh_h);
    cudaGetSymbolAddress((void**)&Wx_h,    g_Wx_h);
    cudaGetSymbolAddress((void**)&Wcomb_h, g_Wcomb_h);
    cudaGetSymbolAddress((void**)&Wfeat_h, g_Wfeat_h);
    cudaGetSymbolAddress((void**)&Wgen_h,  g_Wgen_h);
    cudaGetSymbolAddress((void**)&bcomb,   g_bcomb);
    cudaGetSymbolAddress((void**)&WohT,    g_WohT);
    cudaGetSymbolAddress((void**)&bg,      g_bg);

    // pack weights (fp16) + fp16 batch_H + zero state
    pack_kernel<<<512, 256>>>(W_ih, b_ih, b_hh, W_hid, W_hh, b_hid,
                              W_feat, W_gen, batch_H);

    // feat[BT, H] = batch_H[BT, I] @ W_feat[H, I]^T  -> fp16
    gemm_f16<<<dim3((BB * TT) / 64, HH / 64), 128>>>(
        (const __half*)H_h, Wfeat_h, nullptr, nullptr, 0, 0,
        nullptr, (__half*)feat_h, BB * TT, HH, II, HH);

    for (int s = 0; s < SS; ++s) {
        // Y = h @ [W_hid ; W_hh]^T + [b_hid ; 0]   -> [B, 2560] fp32
        gemm_f16<<<dim3(BB / 64, NCOMB / 64), 128>>>(
            h_h, Wcomb_h, bcomb, nullptr, 0, 0, Y, nullptr, BB, NCOMB, HH, NCOMB);

        // attention: energies + softmax + context (hp = Y[:, :512]) -> fp16 ctx
        att_kernel<<<BB, 256>>>((const uint4*)H_h, (const uint4*)feat_h,
                                Y, NCOMB, w_score, ctx_h);

        // gates = ctx @ Wx^T + (b_ih + b_hh) + Y[:, 512:]  fp32
        gemm_f16<<<dim3(BB / 64, G4H / 64), 128>>>(
            (const __half*)ctx_h, Wx_h, bg, Y, NCOMB, HH, gates, nullptr,
            BB, G4H, II, G4H);

        // LSTM cell (adds one-hot column of W_ih internally)
        lstm_kernel<<<(BB * HH) / 256, 256>>>(gates, WohT, text, s, h_h, c, outh_h);
    }

    // probs[B*S, C] = outh[B*S, H] @ W_gen[C, H]^T + b_gen
    gemm_f16<<<dim3((BB * SS) / 64, (CC + 63) / 64), 128>>>(
        outh_h, Wgen_h, b_gen, nullptr, 0, 0, out, nullptr, BB * SS, CC, HH, CC);
}

// round 7
// speedup vs baseline: 3.3606x; 1.0485x over previous
#include <cuda_runtime.h>
#include <cuda_bf16.h>
#include <cuda_fp16.h>
#include <cstdint>

// Problem constants
#define BB 512
#define TT 128
#define II 512
#define HH 512
#define CC 97
#define SS 26
#define G4H 2048           // 4*H
#define NCOMB 2560         // H + 4H  (W_hid ; W_hh stacked)
#define WIH_LD 609         // I + C

// Interleaved gate index: m = 4*u + g  <->  original row g*512 + u

// ---------------- device scratch (static, no allocs) ----------------
__device__ __half2 g_feat_h[(size_t)BB * TT * HH / 2];   // 64 MB fp16 feat
__device__ __half2 g_H_h[(size_t)BB * TT * II / 2];      // 64 MB fp16 batch_H
__device__ __half  g_h_h[BB * HH];                       // fp16 hidden state
__device__ float   g_c[BB * HH];
__device__ float   g_Y[BB * NCOMB];                      // [hp | h@Whh_il^T] fp32
__device__ __half2 g_ctx_h[BB * II / 2];                 // fp16 context
__device__ __half  g_outh_h[(size_t)BB * SS * HH];       // fp16 step outputs
__device__ __half  g_Wx_h[G4H * II];                     // W_ih[:, :I], gate-interleaved rows
__device__ __half  g_Wcomb_h[NCOMB * HH];                // [W_hid ; W_hh interleaved]
__device__ __half  g_Wfeat_h[HH * II];
__device__ __half  g_Wgen_h[CC * HH];
__device__ float   g_bcomb[NCOMB];                       // [b_hid ; 0]
__device__ float   g_WohT[CC * G4H];                     // W_ih[:, I:]^T interleaved
__device__ float   g_bg[G4H];                            // (b_ih + b_hh) interleaved

// ---------------- pack / init kernel ----------------
__global__ void pack_kernel(const float* __restrict__ W_ih,
                            const float* __restrict__ b_ih,
                            const float* __restrict__ b_hh,
                            const float* __restrict__ W_hid,
                            const float* __restrict__ W_hh,
                            const float* __restrict__ b_hid,
                            const float* __restrict__ W_feat,
                            const float* __restrict__ W_gen,
                            const float* __restrict__ batch_H)
{
    const int stride = gridDim.x * blockDim.x;
    const int t0 = blockIdx.x * blockDim.x + threadIdx.x;
    for (int i = t0; i < G4H * II; i += stride) {
        int n = i >> 9, k = i & 511;
        int u = n >> 2, g = n & 3;
        g_Wx_h[i] = __float2half_rn(W_ih[(g * 512 + u) * WIH_LD + k]);
    }
    for (int i = t0; i < NCOMB * HH; i += stride) {
        int n = i >> 9, k = i & 511;
        float v;
        if (n < HH) v = W_hid[n * HH + k];
        else {
            int m = n - HH, u = m >> 2, g = m & 3;
            v = W_hh[(g * 512 + u) * HH + k];
        }
        g_Wcomb_h[i] = __float2half_rn(v);
    }
    for (int i = t0; i < HH * II; i += stride)
        g_Wfeat_h[i] = __float2half_rn(W_feat[i]);
    for (int i = t0; i < CC * HH; i += stride)
        g_Wgen_h[i] = __float2half_rn(W_gen[i]);
    for (int i = t0; i < CC * G4H; i += stride) {
        int cls = i >> 11, m = i & 2047;
        int u = m >> 2, g = m & 3;
        g_WohT[i] = W_ih[(g * 512 + u) * WIH_LD + II + cls];
    }
    for (int i = t0; i < G4H; i += stride) {
        int u = i >> 2, g = i & 3;
        g_bg[i] = b_ih[g * 512 + u] + b_hh[g * 512 + u];
    }
    for (int i = t0; i < NCOMB; i += stride) g_bcomb[i] = (i < HH) ? b_hid[i] : 0.f;
    for (int i = t0; i < BB * HH; i += stride) {
        g_h_h[i] = __float2half_rn(0.f);
        g_c[i] = 0.f;
    }
    const size_t nh2 = (size_t)BB * TT * II / 2;
    const float2* src = reinterpret_cast<const float2*>(batch_H);
    for (size_t i = t0; i < nh2; i += stride)
        g_H_h[i] = __float22half2_rn(src[i]);
}

#define MMA_F16(d, a, b)                                                         \
    asm volatile("mma.sync.aligned.m16n8k16.row.col.f32.f16.f16.f32 "            \
                 "{%0,%1,%2,%3}, {%4,%5,%6,%7}, {%8,%9}, {%0,%1,%2,%3};"         \
                 : "+f"(d[0]), "+f"(d[1]), "+f"(d[2]), "+f"(d[3])                \
                 : "r"(a[0]), "r"(a[1]), "r"(a[2]), "r"(a[3]),                   \
                   "r"(b[0]), "r"(b[1]))

// ---------------- fp16 GEMM, 64x64 tile, 128 threads ----------------
// C[M,N] = A[M,K] @ B[N,K]^T (+bias[N]); out fp32 C or fp16 Ch.
#define SMP 56

__global__ __launch_bounds__(128)
void gemm_f16(const __half* __restrict__ A, const __half* __restrict__ B,
              const float* __restrict__ bias, float* __restrict__ C,
              __half* __restrict__ Ch,
              int M, int N, int K, int ldc)
{
    __shared__ __half As[2][64][SMP];
    __shared__ __half Bs[2][64][SMP];

    const int tid  = threadIdx.x;
    const int bm   = blockIdx.x * 64;
    const int bn   = blockIdx.y * 64;
    const int w    = tid >> 5, lane = tid & 31;
    const int g    = lane >> 2, tg = lane & 3;
    const int wm   = (w & 1) * 32;
    const int wn   = (w >> 1) * 32;

    float acc[2][4][4];
#pragma unroll
    for (int mt = 0; mt < 2; ++mt)
#pragma unroll
        for (int nt = 0; nt < 4; ++nt)
#pragma unroll
            for (int r = 0; r < 4; ++r) acc[mt][nt][r] = 0.f;

    uint4 stA[2], stB[2];
    const uint4 z4 = make_uint4(0u, 0u, 0u, 0u);
    const int nk = K >> 5;
    const int kld = K >> 3;

    auto ldg = [&](int k0) {
#pragma unroll
        for (int i = 0; i < 2; ++i) {
            int id = tid + i * 128;
            int r = id >> 2, cg = id & 3;
            const uint4* Ar = reinterpret_cast<const uint4*>(A) + (size_t)(bm + r) * kld + (k0 >> 3) + cg;
            const uint4* Br = reinterpret_cast<const uint4*>(B) + (size_t)(bn + r) * kld + (k0 >> 3) + cg;
            stA[i] = (bm + r < M) ? *Ar : z4;
            stB[i] = (bn + r < N) ? *Br : z4;
        }
    };
    auto sts = [&](int buf) {
#pragma unroll
        for (int i = 0; i < 2; ++i) {
            int id = tid + i * 128;
            int r = id >> 2, cg = id & 3;
            *reinterpret_cast<uint4*>(&As[buf][r][cg * 8]) = stA[i];
            *reinterpret_cast<uint4*>(&Bs[buf][r][cg * 8]) = stB[i];
        }
    };

    ldg(0); sts(0);
    __syncthreads();

    for (int kt = 0; kt < nk; ++kt) {
        const int buf = kt & 1;
        if (kt + 1 < nk) ldg((kt + 1) << 5);

#pragma unroll
        for (int ks = 0; ks < 32; ks += 16) {
            unsigned a[2][4];
#pragma unroll
            for (int mt = 0; mt < 2; ++mt) {
                int r0 = wm + mt * 16 + g;
                a[mt][0] = *reinterpret_cast<const unsigned*>(&As[buf][r0][ks + 2 * tg]);
                a[mt][1] = *reinterpret_cast<const unsigned*>(&As[buf][r0 + 8][ks + 2 * tg]);
                a[mt][2] = *reinterpret_cast<const unsigned*>(&As[buf][r0][ks + 8 + 2 * tg]);
                a[mt][3] = *reinterpret_cast<const unsigned*>(&As[buf][r0 + 8][ks + 8 + 2 * tg]);
            }
            unsigned bf[4][2];
#pragma unroll
            for (int nt = 0; nt < 4; ++nt) {
                int n0 = wn + nt * 8 + g;
                bf[nt][0] = *reinterpret_cast<const unsigned*>(&Bs[buf][n0][ks + 2 * tg]);
                bf[nt][1] = *reinterpret_cast<const unsigned*>(&Bs[buf][n0][ks + 8 + 2 * tg]);
            }
#pragma unroll
            for (int mt = 0; mt < 2; ++mt)
#pragma unroll
                for (int nt = 0; nt < 4; ++nt)
                    MMA_F16(acc[mt][nt], a[mt], bf[nt]);
        }

        if (kt + 1 < nk) { __syncthreads(); sts((kt + 1) & 1); }
        __syncthreads();
    }

#pragma unroll
    for (int mt = 0; mt < 2; ++mt)
#pragma unroll
        for (int nt = 0; nt < 4; ++nt)
#pragma unroll
            for (int r = 0; r < 4; ++r) {
                int row = bm + wm + mt * 16 + g + ((r >> 1) << 3);
                int col = bn + wn + nt * 8 + 2 * tg + (r & 1);
                if (row < M && col < N) {
                    float v = acc[mt][nt][r];
                    if (bias) v += bias[col];
                    if (Ch) Ch[(size_t)row * ldc + col] = __float2half_rn(v);
                    else    C [(size_t)row * ldc + col] = v;
                }
            }
}

// ---------------- fp16 GEMM, 128x128 tile, 256 threads (8 warps, 64x32 warp tile) ----------------
#define SMPB 40

__global__ __launch_bounds__(256)
void gemm_f16_big(const __half* __restrict__ A, const __half* __restrict__ B,
                  const float* __restrict__ bias, float* __restrict__ C,
                  __half* __restrict__ Ch,
                  int M, int N, int K, int ldc)
{
    __shared__ __half As[2][128][SMPB];
    __shared__ __half Bs[2][128][SMPB];

    const int tid  = threadIdx.x;
    const int bm   = blockIdx.x * 128;
    const int bn   = blockIdx.y * 128;
    const int w    = tid >> 5, lane = tid & 31;
    const int g    = lane >> 2, tg = lane & 3;
    const int wm   = (w & 1) * 64;       // 2 warps over M
    const int wn   = (w >> 1) * 32;      // 4 warps over N

    float acc[4][4][4];
#pragma unroll
    for (int mt = 0; mt < 4; ++mt)
#pragma unroll
        for (int nt = 0; nt < 4; ++nt)
#pragma unroll
            for (int r = 0; r < 4; ++r) acc[mt][nt][r] = 0.f;

    uint4 stA[2], stB[2];
    const uint4 z4 = make_uint4(0u, 0u, 0u, 0u);
    const int nk = K >> 5;
    const int kld = K >> 3;

    auto ldg = [&](int k0) {
#pragma unroll
        for (int i = 0; i < 2; ++i) {
            int id = tid + i * 256;
            int r = id >> 2, cg = id & 3;
            const uint4* Ar = reinterpret_cast<const uint4*>(A) + (size_t)(bm + r) * kld + (k0 >> 3) + cg;
            const uint4* Br = reinterpret_cast<const uint4*>(B) + (size_t)(bn + r) * kld + (k0 >> 3) + cg;
            stA[i] = (bm + r < M) ? *Ar : z4;
            stB[i] = (bn + r < N) ? *Br : z4;
        }
    };
    auto sts = [&](int buf) {
#pragma unroll
        for (int i = 0; i < 2; ++i) {
            int id = tid + i * 256;
            int r = id >> 2, cg = id & 3;
            *reinterpret_cast<uint4*>(&As[buf][r][cg * 8]) = stA[i];
            *reinterpret_cast<uint4*>(&Bs[buf][r][cg * 8]) = stB[i];
        }
    };

    ldg(0); sts(0);
    __syncthreads();

    for (int kt = 0; kt < nk; ++kt) {
        const int buf = kt & 1;
        if (kt + 1 < nk) ldg((kt + 1) << 5);

#pragma unroll
        for (int ks = 0; ks < 32; ks += 16) {
            unsigned a[4][4];
#pragma unroll
            for (int mt = 0; mt < 4; ++mt) {
                int r0 = wm + mt * 16 + g;
                a[mt][0] = *reinterpret_cast<const unsigned*>(&As[buf][r0][ks + 2 * tg]);
                a[mt][1] = *reinterpret_cast<const unsigned*>(&As[buf][r0 + 8][ks + 2 * tg]);
                a[mt][2] = *reinterpret_cast<const unsigned*>(&As[buf][r0][ks + 8 + 2 * tg]);
                a[mt][3] = *reinterpret_cast<const unsigned*>(&As[buf][r0 + 8][ks + 8 + 2 * tg]);
            }
            unsigned bf[4][2];
#pragma unroll
            for (int nt = 0; nt < 4; ++nt) {
                int n0 = wn + nt * 8 + g;
                bf[nt][0] = *reinterpret_cast<const unsigned*>(&Bs[buf][n0][ks + 2 * tg]);
                bf[nt][1] = *reinterpret_cast<const unsigned*>(&Bs[buf][n0][ks + 8 + 2 * tg]);
            }
#pragma unroll
            for (int mt = 0; mt < 4; ++mt)
#pragma unroll
                for (int nt = 0; nt < 4; ++nt)
                    MMA_F16(acc[mt][nt], a[mt], bf[nt]);
        }

        if (kt + 1 < nk) { __syncthreads(); sts((kt + 1) & 1); }
        __syncthreads();
    }

#pragma unroll
    for (int mt = 0; mt < 4; ++mt)
#pragma unroll
        for (int nt = 0; nt < 4; ++nt)
#pragma unroll
            for (int r = 0; r < 4; ++r) {
                int row = bm + wm + mt * 16 + g + ((r >> 1) << 3);
                int col = bn + wn + nt * 8 + 2 * tg + (r & 1);
                if (row < M && col < N) {
                    float v = acc[mt][nt][r];
                    if (bias) v += bias[col];
                    if (Ch) Ch[(size_t)row * ldc + col] = __float2half_rn(v);
                    else    C [(size_t)row * ldc + col] = v;
                }
            }
}

// ---------------- gates GEMM + fused LSTM cell ----------------
// gates_il[B, 2048] = ctx @ Wx_il^T ; epilogue adds bg_il + Y[:,512+...] + WohT_il[cls]
// then computes the LSTM cell and writes c (fp32), h/outh (fp16).
// Fixed shape: M=512, N=2048, K=512. Grid (8, 32), 128 threads.
__global__ __launch_bounds__(128)
void gemm_gates(const __half* __restrict__ A, const __half* __restrict__ B,
                const float* __restrict__ bg, const float* __restrict__ Y,
                const float* __restrict__ WohT, const int* __restrict__ text, int s,
                float* __restrict__ c, __half* __restrict__ h_h,
                __half* __restrict__ outh_h)
{
    __shared__ __half As[2][64][SMP];
    __shared__ __half Bs[2][64][SMP];
    __shared__ float gsm[64][68];

    const int tid  = threadIdx.x;
    const int bm   = blockIdx.x * 64;
    const int bn   = blockIdx.y * 64;
    const int w    = tid >> 5, lane = tid & 31;
    const int g    = lane >> 2, tg = lane & 3;
    const int wm   = (w & 1) * 32;
    const int wn   = (w >> 1) * 32;

    float acc[2][4][4];
#pragma unroll
    for (int mt = 0; mt < 2; ++mt)
#pragma unroll
        for (int nt = 0; nt < 4; ++nt)
#pragma unroll
            for (int r = 0; r < 4; ++r) acc[mt][nt][r] = 0.f;

    uint4 stA[2], stB[2];
    const int nk = II >> 5;
    const int kld = II >> 3;

    auto ldg = [&](int k0) {
#pragma unroll
        for (int i = 0; i < 2; ++i) {
            int id = tid + i * 128;
            int r = id >> 2, cg = id & 3;
            stA[i] = *(reinterpret_cast<const uint4*>(A) + (size_t)(bm + r) * kld + (k0 >> 3) + cg);
            stB[i] = *(reinterpret_cast<const uint4*>(B) + (size_t)(bn + r) * kld + (k0 >> 3) + cg);
        }
    };
    auto sts = [&](int buf) {
#pragma unroll
        for (int i = 0; i < 2; ++i) {
            int id = tid + i * 128;
            int r = id >> 2, cg = id & 3;
            *reinterpret_cast<uint4*>(&As[buf][r][cg * 8]) = stA[i];
            *reinterpret_cast<uint4*>(&Bs[buf][r][cg * 8]) = stB[i];
        }
    };

    ldg(0); sts(0);
    __syncthreads();

    for (int kt = 0; kt < nk; ++kt) {
        const int buf = kt & 1;
        if (kt + 1 < nk) ldg((kt + 1) << 5);

#pragma unroll
        for (int ks = 0; ks < 32; ks += 16) {
            unsigned a[2][4];
#pragma unroll
            for (int mt = 0; mt < 2; ++mt) {
                int r0 = wm + mt * 16 + g;
                a[mt][0] = *reinterpret_cast<const unsigned*>(&As[buf][r0][ks + 2 * tg]);
                a[mt][1] = *reinterpret_cast<const unsigned*>(&As[buf][r0 + 8][ks + 2 * tg]);
                a[mt][2] = *reinterpret_cast<const unsigned*>(&As[buf][r0][ks + 8 + 2 * tg]);
                a[mt][3] = *reinterpret_cast<const unsigned*>(&As[buf][r0 + 8][ks + 8 + 2 * tg]);
            }
            unsigned bf[4][2];
#pragma unroll
            for (int nt = 0; nt < 4; ++nt) {
                int n0 = wn + nt * 8 + g;
                bf[nt][0] = *reinterpret_cast<const unsigned*>(&Bs[buf][n0][ks + 2 * tg]);
                bf[nt][1] = *reinterpret_cast<const unsigned*>(&Bs[buf][n0][ks + 8 + 2 * tg]);
            }
#pragma unroll
            for (int mt = 0; mt < 2; ++mt)
#pragma unroll
                for (int nt = 0; nt < 4; ++nt)
                    MMA_F16(acc[mt][nt], a[mt], bf[nt]);
        }

        if (kt + 1 < nk) { __syncthreads(); sts((kt + 1) & 1); }
        __syncthreads();
    }

    // stage raw gates into smem
#pragma unroll
    for (int mt = 0; mt < 2; ++mt)
#pragma unroll
        for (int nt = 0; nt < 4; ++nt)
#pragma unroll
            for (int r = 0; r < 4; ++r) {
                int rl = wm + mt * 16 + g + ((r >> 1) << 3);
                int cl = wn + nt * 8 + 2 * tg + (r & 1);
                gsm[rl][cl] = acc[mt][nt][r];
            }
    __syncthreads();

    // fused LSTM: each thread handles 8 (row, unit) items
    {
        const int r  = tid >> 1;            // local row 0..63
        const int u0 = tid & 1;
        const int b  = bm + r;
        const int cls = text[b * SS + s];
        const float4* wo4 = reinterpret_cast<const float4*>(WohT + (size_t)cls * G4H + bn);
        const float4* bg4 = reinterpret_cast<const float4*>(bg + bn);
        const float4* Y4  = reinterpret_cast<const float4*>(Y + (size_t)b * NCOMB + HH + bn);
#pragma unroll
        for (int j = 0; j < 8; ++j) {
            int u = 2 * j + u0;             // 0..15
            float4 gv = *reinterpret_cast<const float4*>(&gsm[r][4 * u]);
            float4 bv = bg4[u];
            float4 yv = Y4[u];
            float4 wv = wo4[u];
            float gi = gv.x + bv.x + yv.x + wv.x;
            float gf = gv.y + bv.y + yv.y + wv.y;
            float gg = gv.z + bv.z + yv.z + wv.z;
            float go = gv.w + bv.w + yv.w + wv.w;

            int ug = (bn >> 2) + u;
            int cidx = b * HH + ug;
            float ci = c[cidx];
            float ig = 1.f / (1.f + expf(-gi));
            float fg = 1.f / (1.f + expf(-gf));
            float og = 1.f / (1.f + expf(-go));
            float c2 = fg * ci + ig * tanhf(gg);
            float h2 = og * tanhf(c2);

            c[cidx] = c2;
            __half h2h = __float2half_rn(h2);
            h_h[cidx] = h2h;
            outh_h[((size_t)b * SS + s) * HH + ug] = h2h;
        }
    }
}

// ---------------- fused attention (fp16, uint4 loads) ----------------
__global__ __launch_bounds__(256)
void att_kernel(const uint4* __restrict__ H4, const uint4* __restrict__ F4,
                const float* __restrict__ hp, int hp_ld,
                const float* __restrict__ w_score, __half2* __restrict__ ctx)
{
    __shared__ float e_sh[TT];
    __shared__ float red_sh[2];
    __shared__ float red4[4][64][8];

    const int b = blockIdx.x;
    const int tid = threadIdx.x;
    const int warp = tid >> 5, lane = tid & 31;

    float2 hpv[8], wsv[8];
    {
        const float2* hp2 = reinterpret_cast<const float2*>(hp + (size_t)b * hp_ld);
        const float2* ws2 = reinterpret_cast<const float2*>(w_score);
#pragma unroll
        for (int j = 0; j < 2; ++j)
#pragma unroll
            for (int q = 0; q < 4; ++q) {
                int idx = 4 * (j * 32 + lane) + q;
                hpv[j * 4 + q] = hp2[idx];
                wsv[j * 4 + q] = ws2[idx];
            }
    }

    for (int t0 = warp; t0 < TT; t0 += 16) {
        const int t1 = t0 + 8;
        const uint4* f0 = F4 + ((size_t)b * TT + t0) * 64;
        const uint4* f1 = F4 + ((size_t)b * TT + t1) * 64;
        uint4 u0a = f0[lane], u0b = f0[32 + lane];
        uint4 u1a = f1[lane], u1b = f1[32 + lane];
        float acc0 = 0.f, acc1 = 0.f;
#pragma unroll
        for (int q = 0; q < 4; ++q) {
            {
                float2 f = __half22float2(reinterpret_cast<const __half2*>(&u0a)[q]);
                float2 hv = hpv[q], wv = wsv[q];
                float a0, a1;
                asm("tanh.approx.f32 %0, %1;" : "=f"(a0) : "f"(f.x + hv.x));
                asm("tanh.approx.f32 %0, %1;" : "=f"(a1) : "f"(f.y + hv.y));
                acc0 = fmaf(a0, wv.x, fmaf(a1, wv.y, acc0));
            }
            {
                float2 f = __half22float2(reinterpret_cast<const __half2*>(&u0b)[q]);
                float2 hv = hpv[4 + q], wv = wsv[4 + q];
                float a0, a1;
                asm("tanh.approx.f32 %0, %1;" : "=f"(a0) : "f"(f.x + hv.x));
                asm("tanh.approx.f32 %0, %1;" : "=f"(a1) : "f"(f.y + hv.y));
                acc0 = fmaf(a0, wv.x, fmaf(a1, wv.y, acc0));
            }
            {
                float2 f = __half22float2(reinterpret_cast<const __half2*>(&u1a)[q]);
                float2 hv = hpv[q], wv = wsv[q];
                float a0, a1;
                asm("tanh.approx.f32 %0, %1;" : "=f"(a0) : "f"(f.x + hv.x));
                asm("tanh.approx.f32 %0, %1;" : "=f"(a1) : "f"(f.y + hv.y));
                acc1 = fmaf(a0, wv.x, fmaf(a1, wv.y, acc1));
            }
            {
                float2 f = __half22float2(reinterpret_cast<const __half2*>(&u1b)[q]);
                float2 hv = hpv[4 + q], wv = wsv[4 + q];
                float a0, a1;
                asm("tanh.approx.f32 %0, %1;" : "=f"(a0) : "f"(f.x + hv.x));
                asm("tanh.approx.f32 %0, %1;" : "=f"(a1) : "f"(f.y + hv.y));
                acc1 = fmaf(a0, wv.x, fmaf(a1, wv.y, acc1));
            }
        }
#pragma unroll
        for (int o = 16; o > 0; o >>= 1) {
            acc0 += __shfl_xor_sync(0xffffffffu, acc0, o);
            acc1 += __shfl_xor_sync(0xffffffffu, acc1, o);
        }
        if (lane == 0) { e_sh[t0] = acc0; e_sh[t1] = acc1; }
    }
    __syncthreads();

    if (tid < 32) {
        float m = fmaxf(fmaxf(e_sh[tid], e_sh[tid + 32]),
                        fmaxf(e_sh[tid + 64], e_sh[tid + 96]));
#pragma unroll
        for (int o = 16; o > 0; o >>= 1) m = fmaxf(m, __shfl_xor_sync(0xffffffffu, m, o));
        if (tid == 0) red_sh[0] = m;
    }
    __syncthreads();
    const float mx = red_sh[0];
    if (tid < TT) e_sh[tid] = __expf(e_sh[tid] - mx);
    __syncthreads();
    if (tid < 32) {
        float ssum = e_sh[tid] + e_sh[tid + 32] + e_sh[tid + 64] + e_sh[tid + 96];
#pragma unroll
        for (int o = 16; o > 0; o >>= 1) ssum += __shfl_xor_sync(0xffffffffu, ssum, o);
        if (tid == 0) red_sh[1] = 1.f / ssum;
    }
    __syncthreads();

    {
        const int tg4 = tid >> 6, ti = tid & 63;
        const uint4* Hb = H4 + (size_t)b * TT * 64 + ti;
        float acc[8];
#pragma unroll
        for (int q = 0; q < 8; ++q) acc[q] = 0.f;
        const int tbeg = tg4 * 32;
#pragma unroll 4
        for (int t = tbeg; t < tbeg + 32; ++t) {
            uint4 u = Hb[(size_t)t * 64];
            float a = e_sh[t];
#pragma unroll
            for (int q = 0; q < 4; ++q) {
                float2 v = __half22float2(reinterpret_cast<const __half2*>(&u)[q]);
                acc[2 * q]     = fmaf(a, v.x, acc[2 * q]);
                acc[2 * q + 1] = fmaf(a, v.y, acc[2 * q + 1]);
            }
        }
#pragma unroll
        for (int q = 0; q < 8; ++q) red4[tg4][ti][q] = acc[q];
    }
    __syncthreads();

    if (tid < 64) {
        const float inv = red_sh[1];
        __half2 o4[4];
#pragma unroll
        for (int q = 0; q < 4; ++q) {
            float x = (red4[0][tid][2*q]   + red4[1][tid][2*q] +
                       red4[2][tid][2*q]   + red4[3][tid][2*q]) * inv;
            float y = (red4[0][tid][2*q+1] + red4[1][tid][2*q+1] +
                       red4[2][tid][2*q+1] + red4[3][tid][2*q+1]) * inv;
            o4[q] = __float22half2_rn(make_float2(x, y));
        }
        *reinterpret_cast<uint4*>(&ctx[(size_t)b * (II / 2) + tid * 4]) =
            *reinterpret_cast<const uint4*>(o4);
    }
}

// ---------------- host launcher ----------------
extern "C" void kernel_launch(void* const* d_in, const int* in_sizes, int n_in,
                              void* d_out, int out_size)
{
    const float* batch_H = (const float*)d_in[0];
    const int*   text    = (const int*)  d_in[1];
    const float* W_feat  = (const float*)d_in[2];
    const float* W_hid   = (const float*)d_in[3];
    const float* b_hid   = (const float*)d_in[4];
    const float* w_score = (const float*)d_in[5];
    const float* W_ih    = (const float*)d_in[6];
    const float* W_hh    = (const float*)d_in[7];
    const float* b_ih    = (const float*)d_in[8];
    const float* b_hh    = (const float*)d_in[9];
    const float* W_gen   = (const float*)d_in[10];
    const float* b_gen   = (const float*)d_in[11];
    float* out = (float*)d_out;

    float *c, *Y, *bcomb, *WohT, *bg;
    __half2 *feat_h, *H_h, *ctx_h;
    __half *h_h, *outh_h, *Wx_h, *Wcomb_h, *Wfeat_h, *Wgen_h;
    cudaGetSymbolAddress((void**)&feat_h,  g_feat_h);
    cudaGetSymbolAddress((void**)&H_h,     g_H_h);
    cudaGetSymbolAddress((void**)&h_h,     g_h_h);
    cudaGetSymbolAddress((void**)&c,       g_c);
    cudaGetSymbolAddress((void**)&Y,       g_Y);
    cudaGetSymbolAddress((void**)&ctx_h,   g_ctx_h);
    cudaGetSymbolAddress((void**)&outh_h,  g_outh_h);
    cudaGetSymbolAddress((void**)&Wx_h,    g_Wx_h);
    cudaGetSymbolAddress((void**)&Wcomb_h, g_Wcomb_h);
    cudaGetSymbolAddress((void**)&Wfeat_h, g_Wfeat_h);
    cudaGetSymbolAddress((void**)&Wgen_h,  g_Wgen_h);
    cudaGetSymbolAddress((void**)&bcomb,   g_bcomb);
    cudaGetSymbolAddress((void**)&WohT,    g_WohT);
    cudaGetSymbolAddress((void**)&bg,      g_bg);

    // pack weights (fp16, gate-interleaved) + fp16 batch_H + zero state
    pack_kernel<<<512, 256>>>(W_ih, b_ih, b_hh, W_hid, W_hh, b_hid,
                              W_feat, W_gen, batch_H);

    // feat[BT, H] = batch_H[BT, I] @ W_feat[H, I]^T  -> fp16 (big-tile kernel)
    gemm_f16_big<<<dim3((BB * TT) / 128, HH / 128), 256>>>(
        (const __half*)H_h, Wfeat_h, nullptr, nullptr, (__half*)feat_h,
        BB * TT, HH, II, HH);

    for (int s = 0; s < SS; ++s) {
        // Y = h @ [W_hid ; W_hh_il]^T + [b_hid ; 0]   -> [B, 2560] fp32
        gemm_f16<<<dim3(BB / 64, NCOMB / 64), 128>>>(
            h_h, Wcomb_h, bcomb, Y, nullptr, BB, NCOMB, HH, NCOMB);

        // attention (hp = Y[:, :512]) -> fp16 ctx
        att_kernel<<<BB, 256>>>((const uint4*)H_h, (const uint4*)feat_h,
                                Y, NCOMB, w_score, ctx_h);

        // gates GEMM + fused LSTM cell
        gemm_gates<<<dim3(BB / 64, G4H / 64), 128>>>(
            (const __half*)ctx_h, Wx_h, bg, Y, WohT, text, s, c, h_h, outh_h);
    }

    // probs[B*S, C] = outh[B*S, H] @ W_gen[C, H]^T + b_gen
    gemm_f16<<<dim3((BB * SS) / 64, (CC + 63) / 64), 128>>>(
        outh_h, Wgen_h, b_gen, out, nullptr, BB * SS, CC, HH, CC);
}